// round 1
// baseline (speedup 1.0000x reference)
#include <cuda_runtime.h>
#include <math.h>

// Problem constants
#define BSZ 16
#define CDIM 512
#define HWD 1024   // 32*32

// Scratch (device globals -- allocation-guard safe)
__device__ float g_q [BSZ * CDIM * HWD];
__device__ float g_k [BSZ * CDIM * HWD];
__device__ float g_v [BSZ * CDIM * HWD];
__device__ float g_s [BSZ * HWD * HWD];
__device__ float g_ao[BSZ * CDIM * HWD];

// ---------------------------------------------------------------------------
// Generic strided batched SGEMM: C[m,n] = alpha * sum_k A[m,k]*B[k,n]
//                                         + bias[m] + resid[m,n]
// Tiles: 128x128x8, 256 threads, 8x8 per-thread microtile.
// All problem dims here divide the tile sizes evenly -> no bounds checks.
// ---------------------------------------------------------------------------
__global__ __launch_bounds__(256)
void sgemm_kernel(const float* __restrict__ A, const float* __restrict__ B,
                  float* __restrict__ C,
                  int M, int N, int K,
                  long sam, long sak, long baA,
                  long sbk, long sbn, long baB,
                  long scm, long scn, long baC,
                  float alpha,
                  const float* __restrict__ bias,
                  const float* __restrict__ resid,
                  long srm, long srn, long baR)
{
    const int BM = 128, BN = 128, BK = 8, TM = 8, TN = 8;

    const int b = blockIdx.z;
    A += (long)b * baA;
    B += (long)b * baB;
    C += (long)b * baC;
    if (resid) resid += (long)b * baR;

    __shared__ float As[BK][BM];
    __shared__ float Bs[BK][BN];

    const int tid  = threadIdx.x;
    const int m0   = blockIdx.y * BM;
    const int n0   = blockIdx.x * BN;
    const int tcol = tid % (BN / TN);  // 0..15
    const int trow = tid / (BN / TN);  // 0..15

    float acc[TM][TN];
    #pragma unroll
    for (int i = 0; i < TM; ++i)
        #pragma unroll
        for (int j = 0; j < TN; ++j)
            acc[i][j] = 0.f;

    for (int k0 = 0; k0 < K; k0 += BK) {
        // ---- load A tile (BM x BK) ----
        if (sam == 1) {
            // m-contiguous: vary m fastest across threads (coalesced)
            #pragma unroll
            for (int i = 0; i < (BM * BK) / 256; ++i) {
                int idx = tid + i * 256;
                int m = idx % BM, kk = idx / BM;
                As[kk][m] = A[(long)(m0 + m) + (long)(k0 + kk) * sak];
            }
        } else {
            // k-contiguous (or strided): vary k fastest
            #pragma unroll
            for (int i = 0; i < (BM * BK) / 256; ++i) {
                int idx = tid + i * 256;
                int kk = idx % BK, m = idx / BK;
                As[kk][m] = A[(long)(m0 + m) * sam + (long)(k0 + kk) * sak];
            }
        }
        // ---- load B tile (BK x BN) ----
        if (sbn == 1) {
            #pragma unroll
            for (int i = 0; i < (BK * BN) / 256; ++i) {
                int idx = tid + i * 256;
                int n = idx % BN, kk = idx / BN;
                Bs[kk][n] = B[(long)(k0 + kk) * sbk + (long)(n0 + n)];
            }
        } else {
            #pragma unroll
            for (int i = 0; i < (BK * BN) / 256; ++i) {
                int idx = tid + i * 256;
                int kk = idx % BK, n = idx / BK;
                Bs[kk][n] = B[(long)(k0 + kk) * sbk + (long)(n0 + n) * sbn];
            }
        }
        __syncthreads();

        // ---- compute ----
        #pragma unroll
        for (int kk = 0; kk < BK; ++kk) {
            float ar[TM], br[TN];
            #pragma unroll
            for (int i = 0; i < TM; ++i) ar[i] = As[kk][trow * TM + i];
            #pragma unroll
            for (int j = 0; j < TN; ++j) br[j] = Bs[kk][tcol * TN + j];
            #pragma unroll
            for (int i = 0; i < TM; ++i)
                #pragma unroll
                for (int j = 0; j < TN; ++j)
                    acc[i][j] = fmaf(ar[i], br[j], acc[i][j]);
        }
        __syncthreads();
    }

    // ---- epilogue ----
    #pragma unroll
    for (int i = 0; i < TM; ++i) {
        const int m = m0 + trow * TM + i;
        const float bi = bias ? bias[m] : 0.f;
        #pragma unroll
        for (int j = 0; j < TN; ++j) {
            const int n = n0 + tcol * TN + j;
            float v = alpha * acc[i][j] + bi;
            if (resid) v += resid[(long)m * srm + (long)n * srn];
            C[(long)m * scm + (long)n * scn] = v;
        }
    }
}

// ---------------------------------------------------------------------------
// Row softmax over 1024 elements; one block (256 threads) per row.
// ---------------------------------------------------------------------------
__global__ __launch_bounds__(256)
void softmax_kernel(float* __restrict__ S)
{
    __shared__ float red[8];

    float* p = S + (long)blockIdx.x * HWD;
    const int t = threadIdx.x;

    float4 v = ((const float4*)p)[t];

    // row max
    float mx = fmaxf(fmaxf(v.x, v.y), fmaxf(v.z, v.w));
    #pragma unroll
    for (int o = 16; o > 0; o >>= 1)
        mx = fmaxf(mx, __shfl_xor_sync(0xFFFFFFFFu, mx, o));
    if ((t & 31) == 0) red[t >> 5] = mx;
    __syncthreads();
    mx = red[0];
    #pragma unroll
    for (int i = 1; i < 8; ++i) mx = fmaxf(mx, red[i]);
    __syncthreads();

    // exp + sum
    v.x = __expf(v.x - mx);
    v.y = __expf(v.y - mx);
    v.z = __expf(v.z - mx);
    v.w = __expf(v.w - mx);
    float sm = v.x + v.y + v.z + v.w;
    #pragma unroll
    for (int o = 16; o > 0; o >>= 1)
        sm += __shfl_xor_sync(0xFFFFFFFFu, sm, o);
    if ((t & 31) == 0) red[t >> 5] = sm;
    __syncthreads();
    sm = red[0];
    #pragma unroll
    for (int i = 1; i < 8; ++i) sm += red[i];

    const float inv = 1.f / sm;
    v.x *= inv; v.y *= inv; v.z *= inv; v.w *= inv;
    ((float4*)p)[t] = v;
}

// ---------------------------------------------------------------------------
extern "C" void kernel_launch(void* const* d_in, const int* in_sizes, int n_in,
                              void* d_out, int out_size)
{
    const float* x  = (const float*)d_in[0];
    const float* Wq = (const float*)d_in[1];
    const float* bq = (const float*)d_in[2];
    const float* Wk = (const float*)d_in[3];
    const float* bk = (const float*)d_in[4];
    const float* Wv = (const float*)d_in[5];
    const float* bv = (const float*)d_in[6];
    const float* Wo = (const float*)d_in[7];
    const float* bo = (const float*)d_in[8];
    float* out = (float*)d_out;

    float *q, *k, *v, *s, *ao;
    cudaGetSymbolAddress((void**)&q,  g_q);
    cudaGetSymbolAddress((void**)&k,  g_k);
    cudaGetSymbolAddress((void**)&v,  g_v);
    cudaGetSymbolAddress((void**)&s,  g_s);
    cudaGetSymbolAddress((void**)&ao, g_ao);

    const long CHW = (long)CDIM * HWD;   // per-batch q/k/v/ao stride
    const long SHW = (long)HWD * HWD;    // per-batch score stride
    const dim3 blk(256);

    // 1) QKV projections: Y[b,o,i] = sum_c W[o,c] * x[b,c,i] + bias[o]
    //    A = W (M=C,K=C): sam=C, sak=1, no batch stride
    //    B = x          : sbk=HW, sbn=1, baB=CHW
    {
        dim3 grd(HWD / 128, CDIM / 128, BSZ);
        sgemm_kernel<<<grd, blk>>>(Wq, x, q, CDIM, HWD, CDIM,
                                   CDIM, 1, 0,   HWD, 1, CHW,   HWD, 1, CHW,
                                   1.0f, bq, nullptr, 0, 0, 0);
        sgemm_kernel<<<grd, blk>>>(Wk, x, k, CDIM, HWD, CDIM,
                                   CDIM, 1, 0,   HWD, 1, CHW,   HWD, 1, CHW,
                                   1.0f, bk, nullptr, 0, 0, 0);
        sgemm_kernel<<<grd, blk>>>(Wv, x, v, CDIM, HWD, CDIM,
                                   CDIM, 1, 0,   HWD, 1, CHW,   HWD, 1, CHW,
                                   1.0f, bv, nullptr, 0, 0, 0);
    }

    // 2) Scores: S[b,i,j] = (1/sqrt(C)) * sum_c q[b,c,i] * k[b,c,j]
    //    A = q (m=i,k=c): sam=1, sak=HW ; B = k (k=c,n=j): sbk=HW, sbn=1
    {
        dim3 grd(HWD / 128, HWD / 128, BSZ);
        const float alpha = 1.0f / sqrtf((float)CDIM);
        sgemm_kernel<<<grd, blk>>>(q, k, s, HWD, HWD, CDIM,
                                   1, HWD, CHW,   HWD, 1, CHW,   HWD, 1, SHW,
                                   alpha, nullptr, nullptr, 0, 0, 0);
    }

    // 3) Softmax over j (rows of length 1024)
    softmax_kernel<<<BSZ * HWD, 256>>>(s);

    // 4) Apply attention: ao[b,c,i] = sum_j v[b,c,j] * attn[b,i,j]
    //    A = v (m=c,k=j): sam=HW, sak=1 ; B = attn (k=j,n=i): sbk=1, sbn=HW
    {
        dim3 grd(HWD / 128, CDIM / 128, BSZ);
        sgemm_kernel<<<grd, blk>>>(v, s, ao, CDIM, HWD, HWD,
                                   HWD, 1, CHW,   1, HWD, SHW,   HWD, 1, CHW,
                                   1.0f, nullptr, nullptr, 0, 0, 0);
    }

    // 5) Output projection + residual:
    //    out[b,o,i] = x[b,o,i] + sum_c Wo[o,c]*ao[b,c,i] + bo[o]
    {
        dim3 grd(HWD / 128, CDIM / 128, BSZ);
        sgemm_kernel<<<grd, blk>>>(Wo, ao, out, CDIM, HWD, CDIM,
                                   CDIM, 1, 0,   HWD, 1, CHW,   HWD, 1, CHW,
                                   1.0f, bo, x, HWD, 1, CHW);
    }
}

// round 2
// speedup vs baseline: 3.5607x; 3.5607x over previous
#include <cuda_runtime.h>
#include <math.h>
#include <stdint.h>

// Problem constants
#define BSZ 16
#define CDIM 512
#define HWD 1024   // 32*32

// Scratch (device globals -- allocation-guard safe)
__device__ float g_q [BSZ * CDIM * HWD];
__device__ float g_k [BSZ * CDIM * HWD];
__device__ float g_v [BSZ * CDIM * HWD];
__device__ float g_s [BSZ * HWD * HWD];
__device__ float g_ao[BSZ * CDIM * HWD];

__device__ __forceinline__ uint32_t f32_to_tf32(float f) {
    uint32_t r;
    asm("cvt.rna.tf32.f32 %0, %1;" : "=r"(r) : "f"(f));
    return r;
}

__device__ __forceinline__ void mma_tf32(float c[4], const uint32_t a[4], const uint32_t b[2]) {
    asm volatile(
        "mma.sync.aligned.m16n8k8.row.col.f32.tf32.tf32.f32 "
        "{%0,%1,%2,%3}, {%4,%5,%6,%7}, {%8,%9}, {%0,%1,%2,%3};\n"
        : "+f"(c[0]), "+f"(c[1]), "+f"(c[2]), "+f"(c[3])
        : "r"(a[0]), "r"(a[1]), "r"(a[2]), "r"(a[3]), "r"(b[0]), "r"(b[1]));
}

// ---------------------------------------------------------------------------
// Generic strided batched GEMM on tf32 tensor cores.
// C[m,n] = alpha * sum_k A[m,k]*B[k,n] + bias[m] + resid[m,n]
// CTA tile 128x128x16, 8 warps in 2x4 layout, warp tile 64x32 (m16n8k8 frags).
// All dims divide tile sizes evenly (M,N multiples of 128; K of 16).
// ---------------------------------------------------------------------------
__global__ __launch_bounds__(256, 2)
void mma_gemm_kernel(const float* __restrict__ A, const float* __restrict__ B,
                     float* __restrict__ C,
                     int M, int N, int K,
                     long sam, long sak, long baA,
                     long sbk, long sbn, long baB,
                     long scm, long scn, long baC,
                     float alpha,
                     const float* __restrict__ bias,
                     const float* __restrict__ resid,
                     long srm, long srn, long baR)
{
    const int BM = 128, BN = 128, BK = 16;
    const int LDS_A = BM + 4;   // padded smem row stride
    const int LDS_B = BN + 4;

    const int b = blockIdx.z;
    A += (long)b * baA;
    B += (long)b * baB;
    C += (long)b * baC;
    if (resid) resid += (long)b * baR;

    __shared__ uint32_t As[BK][BM + 4];
    __shared__ uint32_t Bs[BK][BN + 4];

    const int tid  = threadIdx.x;
    const int lane = tid & 31;
    const int wid  = tid >> 5;
    const int m0   = blockIdx.y * BM;
    const int n0   = blockIdx.x * BN;

    // warp tile origin inside CTA tile: 2 warp-rows x 4 warp-cols
    const int wm0 = (wid >> 2) * 64;   // 0 or 64
    const int wn0 = (wid & 3) * 32;    // 0,32,64,96

    float acc[4][4][4];   // [tm][tn][frag]
    #pragma unroll
    for (int i = 0; i < 4; ++i)
        #pragma unroll
        for (int j = 0; j < 4; ++j)
            #pragma unroll
            for (int r = 0; r < 4; ++r)
                acc[i][j][r] = 0.f;

    for (int k0 = 0; k0 < K; k0 += BK) {
        // ---- load A tile (BM rows x BK cols) ----
        if (sam == 1) {
            #pragma unroll
            for (int i = 0; i < (BM * BK) / 256; ++i) {
                int idx = tid + i * 256;
                int m = idx & (BM - 1), kk = idx >> 7;
                As[kk][m] = f32_to_tf32(A[(long)(m0 + m) + (long)(k0 + kk) * sak]);
            }
        } else {
            #pragma unroll
            for (int i = 0; i < (BM * BK) / 256; ++i) {
                int idx = tid + i * 256;
                int kk = idx & (BK - 1), m = idx >> 4;
                As[kk][m] = f32_to_tf32(A[(long)(m0 + m) * sam + (long)(k0 + kk) * sak]);
            }
        }
        // ---- load B tile (BK rows x BN cols) ----
        if (sbn == 1) {
            #pragma unroll
            for (int i = 0; i < (BK * BN) / 256; ++i) {
                int idx = tid + i * 256;
                int n = idx & (BN - 1), kk = idx >> 7;
                Bs[kk][n] = f32_to_tf32(B[(long)(k0 + kk) * sbk + (long)(n0 + n)]);
            }
        } else {
            #pragma unroll
            for (int i = 0; i < (BK * BN) / 256; ++i) {
                int idx = tid + i * 256;
                int kk = idx & (BK - 1), n = idx >> 4;
                Bs[kk][n] = f32_to_tf32(B[(long)(k0 + kk) * sbk + (long)(n0 + n) * sbn]);
            }
        }
        __syncthreads();

        // ---- compute: 2 sub-steps of k8 ----
        #pragma unroll
        for (int s = 0; s < 2; ++s) {
            const int k8 = s * 8;
            const int kr = k8 + (lane & 3);
            const int mr = lane >> 2;

            uint32_t af[4][4];
            #pragma unroll
            for (int tm = 0; tm < 4; ++tm) {
                const int mb = wm0 + tm * 16 + mr;
                af[tm][0] = As[kr][mb];
                af[tm][1] = As[kr][mb + 8];
                af[tm][2] = As[kr + 4][mb];
                af[tm][3] = As[kr + 4][mb + 8];
            }
            uint32_t bf[4][2];
            #pragma unroll
            for (int tn = 0; tn < 4; ++tn) {
                const int nb = wn0 + tn * 8 + mr;
                bf[tn][0] = Bs[kr][nb];
                bf[tn][1] = Bs[kr + 4][nb];
            }
            #pragma unroll
            for (int tm = 0; tm < 4; ++tm)
                #pragma unroll
                for (int tn = 0; tn < 4; ++tn)
                    mma_tf32(acc[tm][tn], af[tm], bf[tn]);
        }
        __syncthreads();
    }

    // ---- epilogue ----
    #pragma unroll
    for (int tm = 0; tm < 4; ++tm) {
        const int mA = m0 + wm0 + tm * 16 + (lane >> 2);
        const int mB = mA + 8;
        const float biA = bias ? bias[mA] : 0.f;
        const float biB = bias ? bias[mB] : 0.f;
        #pragma unroll
        for (int tn = 0; tn < 4; ++tn) {
            const int n = n0 + wn0 + tn * 8 + 2 * (lane & 3);
            float v0 = alpha * acc[tm][tn][0] + biA;
            float v1 = alpha * acc[tm][tn][1] + biA;
            float v2 = alpha * acc[tm][tn][2] + biB;
            float v3 = alpha * acc[tm][tn][3] + biB;
            if (resid) {
                v0 += resid[(long)mA * srm + (long)n * srn];
                v1 += resid[(long)mA * srm + (long)(n + 1) * srn];
                v2 += resid[(long)mB * srm + (long)n * srn];
                v3 += resid[(long)mB * srm + (long)(n + 1) * srn];
            }
            C[(long)mA * scm + (long)n * scn]       = v0;
            C[(long)mA * scm + (long)(n + 1) * scn] = v1;
            C[(long)mB * scm + (long)n * scn]       = v2;
            C[(long)mB * scm + (long)(n + 1) * scn] = v3;
        }
    }
}

// ---------------------------------------------------------------------------
// Row softmax over 1024 elements; one block (256 threads) per row.
// ---------------------------------------------------------------------------
__global__ __launch_bounds__(256)
void softmax_kernel(float* __restrict__ S)
{
    __shared__ float red[8];

    float* p = S + (long)blockIdx.x * HWD;
    const int t = threadIdx.x;

    float4 v = ((const float4*)p)[t];

    float mx = fmaxf(fmaxf(v.x, v.y), fmaxf(v.z, v.w));
    #pragma unroll
    for (int o = 16; o > 0; o >>= 1)
        mx = fmaxf(mx, __shfl_xor_sync(0xFFFFFFFFu, mx, o));
    if ((t & 31) == 0) red[t >> 5] = mx;
    __syncthreads();
    mx = red[0];
    #pragma unroll
    for (int i = 1; i < 8; ++i) mx = fmaxf(mx, red[i]);
    __syncthreads();

    v.x = __expf(v.x - mx);
    v.y = __expf(v.y - mx);
    v.z = __expf(v.z - mx);
    v.w = __expf(v.w - mx);
    float sm = v.x + v.y + v.z + v.w;
    #pragma unroll
    for (int o = 16; o > 0; o >>= 1)
        sm += __shfl_xor_sync(0xFFFFFFFFu, sm, o);
    if ((t & 31) == 0) red[t >> 5] = sm;
    __syncthreads();
    sm = red[0];
    #pragma unroll
    for (int i = 1; i < 8; ++i) sm += red[i];

    const float inv = 1.f / sm;
    v.x *= inv; v.y *= inv; v.z *= inv; v.w *= inv;
    ((float4*)p)[t] = v;
}

// ---------------------------------------------------------------------------
extern "C" void kernel_launch(void* const* d_in, const int* in_sizes, int n_in,
                              void* d_out, int out_size)
{
    const float* x  = (const float*)d_in[0];
    const float* Wq = (const float*)d_in[1];
    const float* bq = (const float*)d_in[2];
    const float* Wk = (const float*)d_in[3];
    const float* bk = (const float*)d_in[4];
    const float* Wv = (const float*)d_in[5];
    const float* bv = (const float*)d_in[6];
    const float* Wo = (const float*)d_in[7];
    const float* bo = (const float*)d_in[8];
    float* out = (float*)d_out;

    float *q, *k, *v, *s, *ao;
    cudaGetSymbolAddress((void**)&q,  g_q);
    cudaGetSymbolAddress((void**)&k,  g_k);
    cudaGetSymbolAddress((void**)&v,  g_v);
    cudaGetSymbolAddress((void**)&s,  g_s);
    cudaGetSymbolAddress((void**)&ao, g_ao);

    const long CHW = (long)CDIM * HWD;   // per-batch q/k/v/ao stride
    const long SHW = (long)HWD * HWD;    // per-batch score stride
    const dim3 blk(256);

    // 1) QKV projections: Y[b,o,i] = sum_c W[o,c] * x[b,c,i] + bias[o]
    {
        dim3 grd(HWD / 128, CDIM / 128, BSZ);
        mma_gemm_kernel<<<grd, blk>>>(Wq, x, q, CDIM, HWD, CDIM,
                                      CDIM, 1, 0,   HWD, 1, CHW,   HWD, 1, CHW,
                                      1.0f, bq, nullptr, 0, 0, 0);
        mma_gemm_kernel<<<grd, blk>>>(Wk, x, k, CDIM, HWD, CDIM,
                                      CDIM, 1, 0,   HWD, 1, CHW,   HWD, 1, CHW,
                                      1.0f, bk, nullptr, 0, 0, 0);
        mma_gemm_kernel<<<grd, blk>>>(Wv, x, v, CDIM, HWD, CDIM,
                                      CDIM, 1, 0,   HWD, 1, CHW,   HWD, 1, CHW,
                                      1.0f, bv, nullptr, 0, 0, 0);
    }

    // 2) Scores: S[b,i,j] = (1/sqrt(C)) * sum_c q[b,c,i] * k[b,c,j]
    {
        dim3 grd(HWD / 128, HWD / 128, BSZ);
        const float alpha = 1.0f / sqrtf((float)CDIM);
        mma_gemm_kernel<<<grd, blk>>>(q, k, s, HWD, HWD, CDIM,
                                      1, HWD, CHW,   HWD, 1, CHW,   HWD, 1, SHW,
                                      alpha, nullptr, nullptr, 0, 0, 0);
    }

    // 3) Softmax over j (rows of length 1024)
    softmax_kernel<<<BSZ * HWD, 256>>>(s);

    // 4) Apply attention: ao[b,c,i] = sum_j v[b,c,j] * attn[b,i,j]
    {
        dim3 grd(HWD / 128, CDIM / 128, BSZ);
        mma_gemm_kernel<<<grd, blk>>>(v, s, ao, CDIM, HWD, HWD,
                                      HWD, 1, CHW,   1, HWD, SHW,   HWD, 1, CHW,
                                      1.0f, nullptr, nullptr, 0, 0, 0);
    }

    // 5) Output projection + residual
    {
        dim3 grd(HWD / 128, CDIM / 128, BSZ);
        mma_gemm_kernel<<<grd, blk>>>(Wo, ao, out, CDIM, HWD, CDIM,
                                      CDIM, 1, 0,   HWD, 1, CHW,   HWD, 1, CHW,
                                      1.0f, bo, x, HWD, 1, CHW);
    }
}

// round 3
// speedup vs baseline: 4.7337x; 1.3294x over previous
#include <cuda_runtime.h>
#include <math.h>
#include <stdint.h>

// Problem constants
#define BSZ 16
#define CDIM 512
#define HWD 1024   // 32*32

// Scratch (device globals -- allocation-guard safe)
__device__ float g_q [BSZ * CDIM * HWD];
__device__ float g_k [BSZ * CDIM * HWD];
__device__ float g_v [BSZ * CDIM * HWD];
__device__ float g_s [BSZ * HWD * HWD];
__device__ float g_ao[BSZ * CDIM * HWD];

__device__ __forceinline__ uint32_t f32_to_tf32(float f) {
    uint32_t r;
    asm("cvt.rna.tf32.f32 %0, %1;" : "=r"(r) : "f"(f));
    return r;
}

__device__ __forceinline__ void mma_tf32(float c[4], uint32_t a0, uint32_t a1,
                                         uint32_t a2, uint32_t a3,
                                         uint32_t b0, uint32_t b1) {
    asm volatile(
        "mma.sync.aligned.m16n8k8.row.col.f32.tf32.tf32.f32 "
        "{%0,%1,%2,%3}, {%4,%5,%6,%7}, {%8,%9}, {%0,%1,%2,%3};\n"
        : "+f"(c[0]), "+f"(c[1]), "+f"(c[2]), "+f"(c[3])
        : "r"(a0), "r"(a1), "r"(a2), "r"(a3), "r"(b0), "r"(b1));
}

// ---------------------------------------------------------------------------
// Batched GEMM on tf32 tensor cores, layout specialized at compile time.
//   C[m,n] = alpha * sum_k A[m,k]*B[k,n] (+ bias[m]) (+ resid[m,n])
// CTA tile 128x128x16, 8 warps (2x4), warp tile 64x32 of m16n8k8.
// C/resid strides fixed: row stride HWD, col stride 1.
// Smem layout: [buf][k8][kq][m*2+h] where k = k8*8 + kq + 4*h
//   -> fragment gathers are single conflict-free LDS.64s.
// ---------------------------------------------------------------------------
template<int SAM, int SAK, int SBK, int SBN, bool HAS_BIAS, bool HAS_RESID>
__global__ __launch_bounds__(256, 2)
void gemm_tc(const float* __restrict__ A, const float* __restrict__ B,
             float* __restrict__ C, int K,
             long baA, long baB, long baC,
             float alpha,
             const float* __restrict__ bias,
             const float* __restrict__ resid, long baR)
{
    constexpr int SROW = 264;          // padded row (words); 264 % 32 == 8
    __shared__ uint32_t As[2][2][4][SROW];
    __shared__ uint32_t Bs[2][2][4][SROW];

    const int b = blockIdx.z;
    A += (long)b * baA;
    B += (long)b * baB;
    C += (long)b * baC;
    if (HAS_RESID) resid += (long)b * baR;

    const int tid  = threadIdx.x;
    const int lane = tid & 31;
    const int wid  = tid >> 5;
    const int m0   = blockIdx.y * 128;
    const int n0   = blockIdx.x * 128;
    const int wm0  = (wid >> 2) * 64;
    const int wn0  = (wid & 3) * 32;
    const int kq   = lane & 3;
    const int mq   = lane >> 2;

    float acc[4][4][4];
    #pragma unroll
    for (int i = 0; i < 4; ++i)
        #pragma unroll
        for (int j = 0; j < 4; ++j)
            #pragma unroll
            for (int r = 0; r < 4; ++r) acc[i][j][r] = 0.f;

    float4 ra[2], rb[2];

    // ---- global loads into registers for k-tile kt ----
    auto ldg_tile = [&](int kt) {
        const int k0 = kt * 16;
        #pragma unroll
        for (int i = 0; i < 2; ++i) {
            const int c = tid + i * 256;
            if (SAK == 1) {                      // A k-contiguous
                const int m = c >> 2, cq = c & 3;
                ra[i] = *(const float4*)&A[(long)(m0 + m) * SAM + (k0 + 4 * cq)];
            } else {                             // A m-contiguous (SAM==1)
                const int kk = c >> 5, mc = c & 31;
                ra[i] = *(const float4*)&A[(long)(k0 + kk) * SAK + (m0 + 4 * mc)];
            }
            if (SBK == 1) {                      // B k-contiguous
                const int n = c >> 2, cq = c & 3;
                rb[i] = *(const float4*)&B[(long)(n0 + n) * SBN + (k0 + 4 * cq)];
            } else {                             // B n-contiguous (SBN==1)
                const int kk = c >> 5, nc = c & 31;
                rb[i] = *(const float4*)&B[(long)(k0 + kk) * SBK + (n0 + 4 * nc)];
            }
        }
    };

    // ---- store staged registers (as tf32) into smem buffer `buf` ----
    auto sts_tile = [&](int buf) {
        #pragma unroll
        for (int i = 0; i < 2; ++i) {
            const int c = tid + i * 256;
            const float va[4] = { ra[i].x, ra[i].y, ra[i].z, ra[i].w };
            const float vb[4] = { rb[i].x, rb[i].y, rb[i].z, rb[i].w };
            if (SAK == 1) {
                const int m = c >> 2, cq = c & 3;
                const int k8 = cq >> 1, h = cq & 1;
                #pragma unroll
                for (int j = 0; j < 4; ++j)
                    As[buf][k8][j][m * 2 + h] = f32_to_tf32(va[j]);
            } else {
                const int kk = c >> 5, m = (c & 31) * 4;
                const int k8 = kk >> 3, kqi = kk & 3, h = (kk >> 2) & 1;
                #pragma unroll
                for (int j = 0; j < 4; ++j)
                    As[buf][k8][kqi][(m + j) * 2 + h] = f32_to_tf32(va[j]);
            }
            if (SBK == 1) {
                const int n = c >> 2, cq = c & 3;
                const int k8 = cq >> 1, h = cq & 1;
                #pragma unroll
                for (int j = 0; j < 4; ++j)
                    Bs[buf][k8][j][n * 2 + h] = f32_to_tf32(vb[j]);
            } else {
                const int kk = c >> 5, n = (c & 31) * 4;
                const int k8 = kk >> 3, kqi = kk & 3, h = (kk >> 2) & 1;
                #pragma unroll
                for (int j = 0; j < 4; ++j)
                    Bs[buf][k8][kqi][(n + j) * 2 + h] = f32_to_tf32(vb[j]);
            }
        }
    };

    // ---- compute on smem buffer `buf` (two k8 sub-steps) ----
    auto compute_tile = [&](int buf) {
        #pragma unroll
        for (int s = 0; s < 2; ++s) {
            uint2 a0[4], a1[4], b0[4];
            #pragma unroll
            for (int tm = 0; tm < 4; ++tm) {
                const int mb = wm0 + tm * 16 + mq;
                a0[tm] = *(const uint2*)&As[buf][s][kq][mb * 2];
                a1[tm] = *(const uint2*)&As[buf][s][kq][(mb + 8) * 2];
            }
            #pragma unroll
            for (int tn = 0; tn < 4; ++tn) {
                const int nb = wn0 + tn * 8 + mq;
                b0[tn] = *(const uint2*)&Bs[buf][s][kq][nb * 2];
            }
            #pragma unroll
            for (int tm = 0; tm < 4; ++tm)
                #pragma unroll
                for (int tn = 0; tn < 4; ++tn)
                    mma_tf32(acc[tm][tn],
                             a0[tm].x, a1[tm].x, a0[tm].y, a1[tm].y,
                             b0[tn].x, b0[tn].y);
        }
    };

    const int nkt = K >> 4;
    ldg_tile(0);
    sts_tile(0);
    __syncthreads();

    for (int kt = 0; kt < nkt; ++kt) {
        const int cur = kt & 1;
        if (kt + 1 < nkt) ldg_tile(kt + 1);
        compute_tile(cur);
        if (kt + 1 < nkt) {
            sts_tile(cur ^ 1);
            __syncthreads();
        }
    }

    // ---- epilogue (C row stride HWD, col stride 1) ----
    #pragma unroll
    for (int tm = 0; tm < 4; ++tm) {
        const int mA = m0 + wm0 + tm * 16 + mq;
        const int mB = mA + 8;
        const float biA = HAS_BIAS ? bias[mA] : 0.f;
        const float biB = HAS_BIAS ? bias[mB] : 0.f;
        #pragma unroll
        for (int tn = 0; tn < 4; ++tn) {
            const int n = n0 + wn0 + tn * 8 + 2 * kq;
            float2 vA = { alpha * acc[tm][tn][0] + biA,
                          alpha * acc[tm][tn][1] + biA };
            float2 vB = { alpha * acc[tm][tn][2] + biB,
                          alpha * acc[tm][tn][3] + biB };
            if (HAS_RESID) {
                const float2 rA = *(const float2*)&resid[(long)mA * HWD + n];
                const float2 rB = *(const float2*)&resid[(long)mB * HWD + n];
                vA.x += rA.x; vA.y += rA.y;
                vB.x += rB.x; vB.y += rB.y;
            }
            *(float2*)&C[(long)mA * HWD + n] = vA;
            *(float2*)&C[(long)mB * HWD + n] = vB;
        }
    }
}

// ---------------------------------------------------------------------------
// Row softmax over 1024 elements; one block (256 threads) per row.
// ---------------------------------------------------------------------------
__global__ __launch_bounds__(256)
void softmax_kernel(float* __restrict__ S)
{
    __shared__ float red[8];

    float* p = S + (long)blockIdx.x * HWD;
    const int t = threadIdx.x;

    float4 v = ((const float4*)p)[t];

    float mx = fmaxf(fmaxf(v.x, v.y), fmaxf(v.z, v.w));
    #pragma unroll
    for (int o = 16; o > 0; o >>= 1)
        mx = fmaxf(mx, __shfl_xor_sync(0xFFFFFFFFu, mx, o));
    if ((t & 31) == 0) red[t >> 5] = mx;
    __syncthreads();
    mx = red[0];
    #pragma unroll
    for (int i = 1; i < 8; ++i) mx = fmaxf(mx, red[i]);
    __syncthreads();

    v.x = __expf(v.x - mx);
    v.y = __expf(v.y - mx);
    v.z = __expf(v.z - mx);
    v.w = __expf(v.w - mx);
    float sm = v.x + v.y + v.z + v.w;
    #pragma unroll
    for (int o = 16; o > 0; o >>= 1)
        sm += __shfl_xor_sync(0xFFFFFFFFu, sm, o);
    if ((t & 31) == 0) red[t >> 5] = sm;
    __syncthreads();
    sm = red[0];
    #pragma unroll
    for (int i = 1; i < 8; ++i) sm += red[i];

    const float inv = 1.f / sm;
    v.x *= inv; v.y *= inv; v.z *= inv; v.w *= inv;
    ((float4*)p)[t] = v;
}

// ---------------------------------------------------------------------------
extern "C" void kernel_launch(void* const* d_in, const int* in_sizes, int n_in,
                              void* d_out, int out_size)
{
    const float* x  = (const float*)d_in[0];
    const float* Wq = (const float*)d_in[1];
    const float* bq = (const float*)d_in[2];
    const float* Wk = (const float*)d_in[3];
    const float* bk = (const float*)d_in[4];
    const float* Wv = (const float*)d_in[5];
    const float* bv = (const float*)d_in[6];
    const float* Wo = (const float*)d_in[7];
    const float* bo = (const float*)d_in[8];
    float* out = (float*)d_out;

    float *q, *k, *v, *s, *ao;
    cudaGetSymbolAddress((void**)&q,  g_q);
    cudaGetSymbolAddress((void**)&k,  g_k);
    cudaGetSymbolAddress((void**)&v,  g_v);
    cudaGetSymbolAddress((void**)&s,  g_s);
    cudaGetSymbolAddress((void**)&ao, g_ao);

    const long CHW = (long)CDIM * HWD;
    const long SHW = (long)HWD * HWD;
    const dim3 blk(256);

    // 1) QKV projections: q[b,o,i] = sum_c W[o,c]*x[b,c,i] + bias[o]
    //    A=W: sam=CDIM, sak=1 (k-contig). B=x: sbk=HWD, sbn=1 (n-contig).
    {
        dim3 grd(HWD / 128, CDIM / 128, BSZ);
        gemm_tc<CDIM, 1, HWD, 1, true, false><<<grd, blk>>>(
            Wq, x, q, CDIM, 0, CHW, CHW, 1.0f, bq, nullptr, 0);
        gemm_tc<CDIM, 1, HWD, 1, true, false><<<grd, blk>>>(
            Wk, x, k, CDIM, 0, CHW, CHW, 1.0f, bk, nullptr, 0);
        gemm_tc<CDIM, 1, HWD, 1, true, false><<<grd, blk>>>(
            Wv, x, v, CDIM, 0, CHW, CHW, 1.0f, bv, nullptr, 0);
    }

    // 2) Scores: s[b,i,j] = alpha * sum_c q[b,c,i]*k[b,c,j]
    //    A=q: sam=1, sak=HWD (m-contig). B=k: sbk=HWD, sbn=1 (n-contig).
    {
        dim3 grd(HWD / 128, HWD / 128, BSZ);
        const float alpha = 1.0f / sqrtf((float)CDIM);
        gemm_tc<1, HWD, HWD, 1, false, false><<<grd, blk>>>(
            q, k, s, CDIM, CHW, CHW, SHW, alpha, nullptr, nullptr, 0);
    }

    // 3) Softmax over keys
    softmax_kernel<<<BSZ * HWD, 256>>>(s);

    // 4) Apply: ao[b,c,i] = sum_j v[b,c,j]*attn[b,i,j]
    //    A=v: sam=HWD, sak=1 (k-contig). B=attn: sbk=1, sbn=HWD (k-contig).
    {
        dim3 grd(HWD / 128, CDIM / 128, BSZ);
        gemm_tc<HWD, 1, 1, HWD, false, false><<<grd, blk>>>(
            v, s, ao, HWD, CHW, SHW, CHW, 1.0f, nullptr, nullptr, 0);
    }

    // 5) Output projection + residual
    {
        dim3 grd(HWD / 128, CDIM / 128, BSZ);
        gemm_tc<CDIM, 1, HWD, 1, true, true><<<grd, blk>>>(
            Wo, ao, out, CDIM, 0, CHW, CHW, 1.0f, bo, x, CHW);
    }
}

// round 4
// speedup vs baseline: 13.3396x; 2.8180x over previous
#include <cuda_runtime.h>
#include <cuda_bf16.h>
#include <math.h>
#include <stdint.h>

#define BSZ 16
#define CDIM 512
#define HWD 1024   // 32*32

// ---------------- device scratch (allocation-guard safe) -------------------
__device__ float          g_s [BSZ * HWD * HWD];          // fp32 scores
__device__ __nv_bfloat16  g_xb[BSZ * CDIM * HWD];
__device__ __nv_bfloat16  g_qb[BSZ * CDIM * HWD];
__device__ __nv_bfloat16  g_kb[BSZ * CDIM * HWD];
__device__ __nv_bfloat16  g_vb[BSZ * CDIM * HWD];
__device__ __nv_bfloat16  g_ab[BSZ * HWD * HWD];          // attn (bf16)
__device__ __nv_bfloat16  g_ob[BSZ * CDIM * HWD];         // attn@V (bf16)
__device__ __nv_bfloat16  g_wq[CDIM * CDIM];
__device__ __nv_bfloat16  g_wk[CDIM * CDIM];
__device__ __nv_bfloat16  g_wv[CDIM * CDIM];
__device__ __nv_bfloat16  g_wo[CDIM * CDIM];

// ---------------- small helpers --------------------------------------------
__device__ __forceinline__ uint32_t packbf(float lo, float hi) {
    uint32_t r;
    asm("cvt.rn.bf16x2.f32 %0, %1, %2;" : "=r"(r) : "f"(hi), "f"(lo));
    return r;
}
__device__ __forceinline__ void ldm4(uint32_t r[4], uint32_t addr) {
    asm volatile("ldmatrix.sync.aligned.m8n8.x4.shared.b16 {%0,%1,%2,%3}, [%4];"
                 : "=r"(r[0]), "=r"(r[1]), "=r"(r[2]), "=r"(r[3]) : "r"(addr));
}
__device__ __forceinline__ void ldm4t(uint32_t r[4], uint32_t addr) {
    asm volatile("ldmatrix.sync.aligned.m8n8.x4.trans.shared.b16 {%0,%1,%2,%3}, [%4];"
                 : "=r"(r[0]), "=r"(r[1]), "=r"(r[2]), "=r"(r[3]) : "r"(addr));
}
__device__ __forceinline__ void mma_bf16(float c[4], const uint32_t a[4], const uint32_t b[2]) {
    asm volatile(
        "mma.sync.aligned.m16n8k16.row.col.f32.bf16.bf16.f32 "
        "{%0,%1,%2,%3}, {%4,%5,%6,%7}, {%8,%9}, {%0,%1,%2,%3};\n"
        : "+f"(c[0]), "+f"(c[1]), "+f"(c[2]), "+f"(c[3])
        : "r"(a[0]), "r"(a[1]), "r"(a[2]), "r"(a[3]), "r"(b[0]), "r"(b[1]));
}
__device__ __forceinline__ void cpa16(uint32_t dst, const void* src) {
    asm volatile("cp.async.cg.shared.global [%0], [%1], 16;" :: "r"(dst), "l"(src));
}
#define CP_COMMIT() asm volatile("cp.async.commit_group;" ::: "memory")
#define CP_WAIT2()  asm volatile("cp.async.wait_group 2;" ::: "memory")

// ---------------------------------------------------------------------------
// fp32 -> bf16 converter (grid-stride, vectorized)
// ---------------------------------------------------------------------------
__global__ __launch_bounds__(256)
void cvt_kernel(const float4* __restrict__ src, uint2* __restrict__ dst, int n4)
{
    for (int i = blockIdx.x * blockDim.x + threadIdx.x; i < n4;
         i += gridDim.x * blockDim.x) {
        float4 v = src[i];
        uint2 o;
        o.x = packbf(v.x, v.y);
        o.y = packbf(v.z, v.w);
        dst[i] = o;
    }
}

// ---------------------------------------------------------------------------
// Batched bf16 tensor-core GEMM: C[m,n] = alpha*sum_k A[m,k]*B[k,n] (+bias)(+resid)
// CTA tile 128x128x64, 8 warps (2x4), warp tile 64x32, m16n8k16 MMAs.
// 3-stage cp.async pipeline; SW128-style XOR swizzle; ldmatrix fragment loads.
// A_KC: A k-contiguous (addr m*LDA + k); else m-contiguous (addr k*LDA + m).
// B_NC: B n-contiguous (addr k*LDB + n); else k-contiguous (addr n*LDB + k).
// C row stride HWD, col contiguous. OUT_F32 selects output type.
// ---------------------------------------------------------------------------
template<bool A_KC, bool B_NC, int LDA, int LDB, bool BIAS, bool RESID, bool OUT_F32>
__global__ __launch_bounds__(256, 2)
void gemm_bf16(const __nv_bfloat16* __restrict__ A,
               const __nv_bfloat16* __restrict__ B,
               void* __restrict__ Cv, int K,
               long baA, long baB, long baC,
               float alpha, const float* __restrict__ bias,
               const float* __restrict__ resid, long baR)
{
    extern __shared__ uint8_t smem[];
    const uint32_t smem_u = (uint32_t)__cvta_generic_to_shared(smem);
    const int STAGE = 32768;            // 16KB A + 16KB B

    const int b = blockIdx.z;
    A += (long)b * baA;
    B += (long)b * baB;
    if (RESID) resid += (long)b * baR;

    const int tid  = threadIdx.x;
    const int lane = tid & 31;
    const int wid  = tid >> 5;
    const int m0   = blockIdx.y * 128;
    const int n0   = blockIdx.x * 128;
    const int wm0  = (wid >> 2) * 64;
    const int wn0  = (wid & 3) * 32;

    float acc[4][4][4];
    #pragma unroll
    for (int i = 0; i < 4; ++i)
        #pragma unroll
        for (int j = 0; j < 4; ++j)
            #pragma unroll
            for (int r = 0; r < 4; ++r) acc[i][j][r] = 0.f;

    // ---- cp.async tile fill: 1024 16B units per operand, 4 per thread ----
    auto fill = [&](int kt, int buf) {
        const int k0 = kt * 64;
        const uint32_t Ab = smem_u + buf * STAGE;
        const uint32_t Bb = Ab + 16384;
        #pragma unroll
        for (int i = 0; i < 4; ++i) {
            const int g = tid + i * 256;
            // A
            if (A_KC) {
                const int m = g >> 3, u = g & 7;
                cpa16(Ab + m * 128 + ((u ^ (m & 7)) << 4),
                      A + (long)(m0 + m) * LDA + k0 + u * 8);
            } else {
                const int kk = g >> 4, u = g & 15;
                cpa16(Ab + kk * 256 + ((u ^ (kk & 7)) << 4),
                      A + (long)(k0 + kk) * LDA + m0 + u * 8);
            }
            // B
            if (B_NC) {
                const int kk = g >> 4, u = g & 15;
                cpa16(Bb + kk * 256 + ((u ^ (kk & 7)) << 4),
                      B + (long)(k0 + kk) * LDB + n0 + u * 8);
            } else {
                const int n = g >> 3, u = g & 7;
                cpa16(Bb + n * 128 + ((u ^ (n & 7)) << 4),
                      B + (long)(n0 + n) * LDB + k0 + u * 8);
            }
        }
        CP_COMMIT();
    };

    // ---- compute one 64-deep k-tile from smem buffer `buf` ----
    auto compute = [&](int buf) {
        const uint32_t Ab = smem_u + buf * STAGE;
        const uint32_t Bb = Ab + 16384;
        #pragma unroll
        for (int s = 0; s < 4; ++s) {
            uint32_t af[4][4];
            #pragma unroll
            for (int tm = 0; tm < 4; ++tm) {
                if (A_KC) {
                    const int m_row = wm0 + tm * 16 + (lane & 15);
                    const int u = 2 * s + (lane >> 4);
                    ldm4(af[tm], Ab + m_row * 128 + ((u ^ (m_row & 7)) << 4));
                } else {
                    const int k_row = s * 16 + (lane & 7) + ((lane >> 4) & 1) * 8;
                    const int u = ((wm0 + tm * 16) >> 3) + ((lane >> 3) & 1);
                    ldm4t(af[tm], Ab + k_row * 256 + ((u ^ (k_row & 7)) << 4));
                }
            }
            uint32_t bf[4][2];
            #pragma unroll
            for (int tb = 0; tb < 2; ++tb) {
                uint32_t r[4];
                if (B_NC) {
                    const int k_row = s * 16 + (lane & 7) + ((lane >> 3) & 1) * 8;
                    const int u = ((wn0 + tb * 16) >> 3) + ((lane >> 4) & 1);
                    ldm4t(r, Bb + k_row * 256 + ((u ^ (k_row & 7)) << 4));
                } else {
                    const int n_row = wn0 + tb * 16 + (lane & 7) + ((lane >> 4) & 1) * 8;
                    const int u = 2 * s + ((lane >> 3) & 1);
                    ldm4(r, Bb + n_row * 128 + ((u ^ (n_row & 7)) << 4));
                }
                bf[tb * 2][0] = r[0]; bf[tb * 2][1] = r[1];
                bf[tb * 2 + 1][0] = r[2]; bf[tb * 2 + 1][1] = r[3];
            }
            #pragma unroll
            for (int tm = 0; tm < 4; ++tm)
                #pragma unroll
                for (int tn = 0; tn < 4; ++tn)
                    mma_bf16(acc[tm][tn], af[tm], bf[tn]);
        }
    };

    const int nkt = K >> 6;
    #pragma unroll
    for (int p = 0; p < 3; ++p) {
        if (p < nkt) fill(p, p); else CP_COMMIT();
    }

    for (int kt = 0; kt < nkt; ++kt) {
        CP_WAIT2();
        __syncthreads();
        compute(kt % 3);
        __syncthreads();
        const int nt = kt + 3;
        if (nt < nkt) fill(nt, kt % 3); else CP_COMMIT();
    }

    // ---- epilogue ----
    const int kq = lane & 3;
    const int mq = lane >> 2;
    #pragma unroll
    for (int tm = 0; tm < 4; ++tm) {
        const int mA = m0 + wm0 + tm * 16 + mq;
        const int mB = mA + 8;
        const float biA = BIAS ? bias[mA] : 0.f;
        const float biB = BIAS ? bias[mB] : 0.f;
        #pragma unroll
        for (int tn = 0; tn < 4; ++tn) {
            const int n = n0 + wn0 + tn * 8 + 2 * kq;
            float v0 = alpha * acc[tm][tn][0] + biA;
            float v1 = alpha * acc[tm][tn][1] + biA;
            float v2 = alpha * acc[tm][tn][2] + biB;
            float v3 = alpha * acc[tm][tn][3] + biB;
            if (RESID) {
                const float2 rA = *(const float2*)&resid[(long)mA * HWD + n];
                const float2 rB = *(const float2*)&resid[(long)mB * HWD + n];
                v0 += rA.x; v1 += rA.y; v2 += rB.x; v3 += rB.y;
            }
            if (OUT_F32) {
                float* C = (float*)Cv + (long)b * baC;
                *(float2*)&C[(long)mA * HWD + n] = make_float2(v0, v1);
                *(float2*)&C[(long)mB * HWD + n] = make_float2(v2, v3);
            } else {
                __nv_bfloat16* C = (__nv_bfloat16*)Cv + (long)b * baC;
                *(uint32_t*)&C[(long)mA * HWD + n] = packbf(v0, v1);
                *(uint32_t*)&C[(long)mB * HWD + n] = packbf(v2, v3);
            }
        }
    }
}

// ---------------------------------------------------------------------------
// Row softmax (1024 keys): fp32 in, bf16 out. One 256-thread block per row.
// ---------------------------------------------------------------------------
__global__ __launch_bounds__(256)
void softmax_kernel(const float* __restrict__ S, __nv_bfloat16* __restrict__ P)
{
    __shared__ float red[8];

    const float* p = S + (long)blockIdx.x * HWD;
    const int t = threadIdx.x;

    float4 v = ((const float4*)p)[t];

    float mx = fmaxf(fmaxf(v.x, v.y), fmaxf(v.z, v.w));
    #pragma unroll
    for (int o = 16; o > 0; o >>= 1)
        mx = fmaxf(mx, __shfl_xor_sync(0xFFFFFFFFu, mx, o));
    if ((t & 31) == 0) red[t >> 5] = mx;
    __syncthreads();
    mx = red[0];
    #pragma unroll
    for (int i = 1; i < 8; ++i) mx = fmaxf(mx, red[i]);
    __syncthreads();

    v.x = __expf(v.x - mx);
    v.y = __expf(v.y - mx);
    v.z = __expf(v.z - mx);
    v.w = __expf(v.w - mx);
    float sm = v.x + v.y + v.z + v.w;
    #pragma unroll
    for (int o = 16; o > 0; o >>= 1)
        sm += __shfl_xor_sync(0xFFFFFFFFu, sm, o);
    if ((t & 31) == 0) red[t >> 5] = sm;
    __syncthreads();
    sm = red[0];
    #pragma unroll
    for (int i = 1; i < 8; ++i) sm += red[i];

    const float inv = 1.f / sm;
    uint2 o;
    o.x = packbf(v.x * inv, v.y * inv);
    o.y = packbf(v.z * inv, v.w * inv);
    ((uint2*)(P + (long)blockIdx.x * HWD))[t] = o;
}

// ---------------------------------------------------------------------------
extern "C" void kernel_launch(void* const* d_in, const int* in_sizes, int n_in,
                              void* d_out, int out_size)
{
    const float* x  = (const float*)d_in[0];
    const float* Wq = (const float*)d_in[1];
    const float* bq = (const float*)d_in[2];
    const float* Wk = (const float*)d_in[3];
    const float* bk = (const float*)d_in[4];
    const float* Wv = (const float*)d_in[5];
    const float* bv = (const float*)d_in[6];
    const float* Wo = (const float*)d_in[7];
    const float* bo = (const float*)d_in[8];
    float* out = (float*)d_out;

    float *s;
    __nv_bfloat16 *xb, *qb, *kb, *vb, *ab, *ob, *wq, *wk, *wv, *wo;
    cudaGetSymbolAddress((void**)&s,  g_s);
    cudaGetSymbolAddress((void**)&xb, g_xb);
    cudaGetSymbolAddress((void**)&qb, g_qb);
    cudaGetSymbolAddress((void**)&kb, g_kb);
    cudaGetSymbolAddress((void**)&vb, g_vb);
    cudaGetSymbolAddress((void**)&ab, g_ab);
    cudaGetSymbolAddress((void**)&ob, g_ob);
    cudaGetSymbolAddress((void**)&wq, g_wq);
    cudaGetSymbolAddress((void**)&wk, g_wk);
    cudaGetSymbolAddress((void**)&wv, g_wv);
    cudaGetSymbolAddress((void**)&wo, g_wo);

    const long CHW = (long)CDIM * HWD;
    const long SHW = (long)HWD * HWD;
    const int  SMEM = 3 * 32768;
    const dim3 blk(256);

    // kernel instantiations + smem attribute
    auto kProj  = gemm_bf16<true,  true,  CDIM, HWD, true,  false, false>;
    auto kScore = gemm_bf16<false, true,  HWD,  HWD, false, false, true >;
    auto kAV    = gemm_bf16<true,  false, HWD,  HWD, false, false, false>;
    auto kOut   = gemm_bf16<true,  true,  CDIM, HWD, true,  true,  true >;
    cudaFuncSetAttribute(kProj,  cudaFuncAttributeMaxDynamicSharedMemorySize, SMEM);
    cudaFuncSetAttribute(kScore, cudaFuncAttributeMaxDynamicSharedMemorySize, SMEM);
    cudaFuncSetAttribute(kAV,    cudaFuncAttributeMaxDynamicSharedMemorySize, SMEM);
    cudaFuncSetAttribute(kOut,   cudaFuncAttributeMaxDynamicSharedMemorySize, SMEM);

    // 0) converts
    cvt_kernel<<<512, 256>>>((const float4*)x,  (uint2*)xb, (int)(CHW * BSZ / 4));
    cvt_kernel<<<128, 256>>>((const float4*)Wq, (uint2*)wq, CDIM * CDIM / 4);
    cvt_kernel<<<128, 256>>>((const float4*)Wk, (uint2*)wk, CDIM * CDIM / 4);
    cvt_kernel<<<128, 256>>>((const float4*)Wv, (uint2*)wv, CDIM * CDIM / 4);
    cvt_kernel<<<128, 256>>>((const float4*)Wo, (uint2*)wo, CDIM * CDIM / 4);

    // 1) QKV projections -> bf16
    {
        dim3 grd(HWD / 128, CDIM / 128, BSZ);
        kProj<<<grd, blk, SMEM>>>(wq, xb, qb, CDIM, 0, CHW, CHW, 1.f, bq, nullptr, 0);
        kProj<<<grd, blk, SMEM>>>(wk, xb, kb, CDIM, 0, CHW, CHW, 1.f, bk, nullptr, 0);
        kProj<<<grd, blk, SMEM>>>(wv, xb, vb, CDIM, 0, CHW, CHW, 1.f, bv, nullptr, 0);
    }

    // 2) Scores (fp32 out, scaled)
    {
        dim3 grd(HWD / 128, HWD / 128, BSZ);
        const float alpha = 1.0f / sqrtf((float)CDIM);
        kScore<<<grd, blk, SMEM>>>(qb, kb, s, CDIM, CHW, CHW, SHW, alpha,
                                   nullptr, nullptr, 0);
    }

    // 3) Softmax -> bf16 attn
    softmax_kernel<<<BSZ * HWD, 256>>>(s, ab);

    // 4) attn @ V -> bf16
    {
        dim3 grd(HWD / 128, CDIM / 128, BSZ);
        kAV<<<grd, blk, SMEM>>>(vb, ab, ob, HWD, CHW, SHW, CHW, 1.f,
                                nullptr, nullptr, 0);
    }

    // 5) Output projection + bias + residual (fp32 out)
    {
        dim3 grd(HWD / 128, CDIM / 128, BSZ);
        kOut<<<grd, blk, SMEM>>>(wo, ob, out, CDIM, 0, CHW, CHW, 1.f,
                                 bo, x, CHW);
    }
}

// round 6
// speedup vs baseline: 15.3331x; 1.1494x over previous
#include <cuda_runtime.h>
#include <cuda_bf16.h>
#include <math.h>
#include <stdint.h>

#define BSZ 16
#define CDIM 512
#define HWD 1024   // 32*32

// ---------------- device scratch (allocation-guard safe) -------------------
__device__ float          g_s  [BSZ * HWD * HWD];            // fp32 scores
__device__ __nv_bfloat16  g_xb [BSZ * CDIM * HWD];           // x bf16 [b][c][i]
__device__ __nv_bfloat16  g_qkv[BSZ * 3 * CDIM * HWD];       // q|k|v [b][3c][i]
__device__ __nv_bfloat16  g_ab [BSZ * HWD * HWD];            // attn bf16 [b][i][j]
__device__ __nv_bfloat16  g_ob [BSZ * CDIM * HWD];           // attn@V bf16 [b][c][i]
__device__ __nv_bfloat16  g_w  [4][CDIM * CDIM];             // Wq,Wk,Wv (contig 1536x512), Wo
__device__ float          g_bqkv[3 * CDIM];                  // packed bq|bk|bv

// ---------------- small helpers --------------------------------------------
__device__ __forceinline__ uint32_t packbf(float lo, float hi) {
    uint32_t r;
    asm("cvt.rn.bf16x2.f32 %0, %1, %2;" : "=r"(r) : "f"(hi), "f"(lo));
    return r;
}
__device__ __forceinline__ void ldm4(uint32_t r[4], uint32_t addr) {
    asm volatile("ldmatrix.sync.aligned.m8n8.x4.shared.b16 {%0,%1,%2,%3}, [%4];"
                 : "=r"(r[0]), "=r"(r[1]), "=r"(r[2]), "=r"(r[3]) : "r"(addr));
}
__device__ __forceinline__ void ldm4t(uint32_t r[4], uint32_t addr) {
    asm volatile("ldmatrix.sync.aligned.m8n8.x4.trans.shared.b16 {%0,%1,%2,%3}, [%4];"
                 : "=r"(r[0]), "=r"(r[1]), "=r"(r[2]), "=r"(r[3]) : "r"(addr));
}
__device__ __forceinline__ void mma_bf16(float c[4], const uint32_t a[4], const uint32_t b[2]) {
    asm volatile(
        "mma.sync.aligned.m16n8k16.row.col.f32.bf16.bf16.f32 "
        "{%0,%1,%2,%3}, {%4,%5,%6,%7}, {%8,%9}, {%0,%1,%2,%3};\n"
        : "+f"(c[0]), "+f"(c[1]), "+f"(c[2]), "+f"(c[3])
        : "r"(a[0]), "r"(a[1]), "r"(a[2]), "r"(a[3]), "r"(b[0]), "r"(b[1]));
}
__device__ __forceinline__ void cpa16(uint32_t dst, const void* src) {
    asm volatile("cp.async.cg.shared.global [%0], [%1], 16;" :: "r"(dst), "l"(src));
}
#define CP_COMMIT() asm volatile("cp.async.commit_group;" ::: "memory")
#define CP_WAIT2()  asm volatile("cp.async.wait_group 2;" ::: "memory")

// ---------------------------------------------------------------------------
// fp32 -> bf16 converter (grid-stride, vectorized)
// ---------------------------------------------------------------------------
__global__ __launch_bounds__(256)
void cvt_kernel(const float4* __restrict__ src, uint2* __restrict__ dst, int n4)
{
    for (int i = blockIdx.x * blockDim.x + threadIdx.x; i < n4;
         i += gridDim.x * blockDim.x) {
        float4 v = src[i];
        uint2 o;
        o.x = packbf(v.x, v.y);
        o.y = packbf(v.z, v.w);
        dst[i] = o;
    }
}

// Weight convert: 4 x [512x512] f32 -> bf16 into contiguous g_w
__global__ __launch_bounds__(256)
void cvt_w_kernel(const float4* __restrict__ w0, const float4* __restrict__ w1,
                  const float4* __restrict__ w2, const float4* __restrict__ w3,
                  uint2* __restrict__ dst)
{
    const int which = blockIdx.y;
    const float4* src = which == 0 ? w0 : which == 1 ? w1 : which == 2 ? w2 : w3;
    const int i = blockIdx.x * 256 + threadIdx.x;   // < 65536
    float4 v = src[i];
    uint2 o;
    o.x = packbf(v.x, v.y);
    o.y = packbf(v.z, v.w);
    dst[which * (CDIM * CDIM / 4) + i] = o;
}

// Pack bq|bk|bv into one 1536-float vector
__global__ __launch_bounds__(512)
void pack_bias_kernel(const float* __restrict__ a, const float* __restrict__ b,
                      const float* __restrict__ c, float* __restrict__ dst)
{
    const float* src = blockIdx.x == 0 ? a : blockIdx.x == 1 ? b : c;
    dst[blockIdx.x * CDIM + threadIdx.x] = src[threadIdx.x];
}

// ---------------------------------------------------------------------------
// Batched bf16 tensor-core GEMM: C[m,n] = alpha*sum_k A[m,k]*B[k,n] (+bias)(+resid)
// CTA tile 128x128x64, 4 warps (2x2), warp tile 64x64, m16n8k16 MMAs.
// 3-stage cp.async pipeline; XOR swizzle; ldmatrix fragment loads.
// A_KC: A k-contiguous (addr m*LDA + k); else m-contiguous (addr k*LDA + m).
// B_NC: B n-contiguous (addr k*LDB + n); else k-contiguous (addr n*LDB + k).
// C row stride HWD, col contiguous. OUT_F32 selects output type.
// ---------------------------------------------------------------------------
template<bool A_KC, bool B_NC, int LDA, int LDB, bool BIAS, bool RESID, bool OUT_F32>
__global__ __launch_bounds__(128, 2)
void gemm_bf16(const __nv_bfloat16* __restrict__ A,
               const __nv_bfloat16* __restrict__ B,
               void* __restrict__ Cv, int K,
               long baA, long baB, long baC,
               float alpha, const float* __restrict__ bias,
               const float* __restrict__ resid, long baR)
{
    extern __shared__ uint8_t smem[];
    const uint32_t smem_u = (uint32_t)__cvta_generic_to_shared(smem);
    const int STAGE = 32768;            // 16KB A + 16KB B

    const int b = blockIdx.z;
    A += (long)b * baA;
    B += (long)b * baB;
    if (RESID) resid += (long)b * baR;

    const int tid  = threadIdx.x;
    const int lane = tid & 31;
    const int wid  = tid >> 5;          // 0..3
    const int m0   = blockIdx.y * 128;
    const int n0   = blockIdx.x * 128;
    const int wm0  = (wid >> 1) * 64;   // 0 or 64
    const int wn0  = (wid & 1) * 64;    // 0 or 64

    float acc[4][8][4];
    #pragma unroll
    for (int i = 0; i < 4; ++i)
        #pragma unroll
        for (int j = 0; j < 8; ++j)
            #pragma unroll
            for (int r = 0; r < 4; ++r) acc[i][j][r] = 0.f;

    // ---- cp.async tile fill: 1024 16B units per operand, 8 per thread ----
    auto fill = [&](int kt, int buf) {
        const int k0 = kt * 64;
        const uint32_t Ab = smem_u + buf * STAGE;
        const uint32_t Bb = Ab + 16384;
        #pragma unroll
        for (int i = 0; i < 8; ++i) {
            const int g = tid + i * 128;
            // A
            if (A_KC) {
                const int m = g >> 3, u = g & 7;
                cpa16(Ab + m * 128 + ((u ^ (m & 7)) << 4),
                      A + (long)(m0 + m) * LDA + k0 + u * 8);
            } else {
                const int kk = g >> 4, u = g & 15;
                cpa16(Ab + kk * 256 + ((u ^ (kk & 7)) << 4),
                      A + (long)(k0 + kk) * LDA + m0 + u * 8);
            }
            // B
            if (B_NC) {
                const int kk = g >> 4, u = g & 15;
                cpa16(Bb + kk * 256 + ((u ^ (kk & 7)) << 4),
                      B + (long)(k0 + kk) * LDB + n0 + u * 8);
            } else {
                const int n = g >> 3, u = g & 7;
                cpa16(Bb + n * 128 + ((u ^ (n & 7)) << 4),
                      B + (long)(n0 + n) * LDB + k0 + u * 8);
            }
        }
        CP_COMMIT();
    };

    // ---- compute one 64-deep k-tile from smem buffer `buf` ----
    auto compute = [&](int buf) {
        const uint32_t Ab = smem_u + buf * STAGE;
        const uint32_t Bb = Ab + 16384;
        #pragma unroll
        for (int s = 0; s < 4; ++s) {
            uint32_t af[4][4];
            #pragma unroll
            for (int tm = 0; tm < 4; ++tm) {
                if (A_KC) {
                    const int m_row = wm0 + tm * 16 + (lane & 15);
                    const int u = 2 * s + (lane >> 4);
                    ldm4(af[tm], Ab + m_row * 128 + ((u ^ (m_row & 7)) << 4));
                } else {
                    const int k_row = s * 16 + (lane & 7) + ((lane >> 4) & 1) * 8;
                    const int u = ((wm0 + tm * 16) >> 3) + ((lane >> 3) & 1);
                    ldm4t(af[tm], Ab + k_row * 256 + ((u ^ (k_row & 7)) << 4));
                }
            }
            uint32_t bf[8][2];
            #pragma unroll
            for (int tb = 0; tb < 4; ++tb) {
                uint32_t r[4];
                if (B_NC) {
                    const int k_row = s * 16 + (lane & 7) + ((lane >> 3) & 1) * 8;
                    const int u = ((wn0 + tb * 16) >> 3) + ((lane >> 4) & 1);
                    ldm4t(r, Bb + k_row * 256 + ((u ^ (k_row & 7)) << 4));
                } else {
                    const int n_row = wn0 + tb * 16 + (lane & 7) + ((lane >> 4) & 1) * 8;
                    const int u = 2 * s + ((lane >> 3) & 1);
                    ldm4(r, Bb + n_row * 128 + ((u ^ (n_row & 7)) << 4));
                }
                bf[tb * 2][0] = r[0]; bf[tb * 2][1] = r[1];
                bf[tb * 2 + 1][0] = r[2]; bf[tb * 2 + 1][1] = r[3];
            }
            #pragma unroll
            for (int tm = 0; tm < 4; ++tm)
                #pragma unroll
                for (int tn = 0; tn < 8; ++tn)
                    mma_bf16(acc[tm][tn], af[tm], bf[tn]);
        }
    };

    const int nkt = K >> 6;
    #pragma unroll
    for (int p = 0; p < 3; ++p) {
        if (p < nkt) fill(p, p); else CP_COMMIT();
    }

    for (int kt = 0; kt < nkt; ++kt) {
        CP_WAIT2();
        __syncthreads();
        compute(kt % 3);
        __syncthreads();
        const int nt = kt + 3;
        if (nt < nkt) fill(nt, kt % 3); else CP_COMMIT();
    }

    // ---- epilogue ----
    const int kq = lane & 3;
    const int mq = lane >> 2;
    #pragma unroll
    for (int tm = 0; tm < 4; ++tm) {
        const int mA = m0 + wm0 + tm * 16 + mq;
        const int mB = mA + 8;
        const float biA = BIAS ? bias[mA] : 0.f;
        const float biB = BIAS ? bias[mB] : 0.f;
        #pragma unroll
        for (int tn = 0; tn < 8; ++tn) {
            const int n = n0 + wn0 + tn * 8 + 2 * kq;
            float v0 = alpha * acc[tm][tn][0] + biA;
            float v1 = alpha * acc[tm][tn][1] + biA;
            float v2 = alpha * acc[tm][tn][2] + biB;
            float v3 = alpha * acc[tm][tn][3] + biB;
            if (RESID) {
                const float2 rA = *(const float2*)&resid[(long)mA * HWD + n];
                const float2 rB = *(const float2*)&resid[(long)mB * HWD + n];
                v0 += rA.x; v1 += rA.y; v2 += rB.x; v3 += rB.y;
            }
            if (OUT_F32) {
                float* C = (float*)Cv + (long)b * baC;
                *(float2*)&C[(long)mA * HWD + n] = make_float2(v0, v1);
                *(float2*)&C[(long)mB * HWD + n] = make_float2(v2, v3);
            } else {
                __nv_bfloat16* C = (__nv_bfloat16*)Cv + (long)b * baC;
                *(uint32_t*)&C[(long)mA * HWD + n] = packbf(v0, v1);
                *(uint32_t*)&C[(long)mB * HWD + n] = packbf(v2, v3);
            }
        }
    }
}

// ---------------------------------------------------------------------------
// Row softmax (1024 keys): fp32 in, bf16 out. One 256-thread block per row.
// ---------------------------------------------------------------------------
__global__ __launch_bounds__(256)
void softmax_kernel(const float* __restrict__ S, __nv_bfloat16* __restrict__ P)
{
    __shared__ float red[8];

    const float* p = S + (long)blockIdx.x * HWD;
    const int t = threadIdx.x;

    float4 v = ((const float4*)p)[t];

    float mx = fmaxf(fmaxf(v.x, v.y), fmaxf(v.z, v.w));
    #pragma unroll
    for (int o = 16; o > 0; o >>= 1)
        mx = fmaxf(mx, __shfl_xor_sync(0xFFFFFFFFu, mx, o));
    if ((t & 31) == 0) red[t >> 5] = mx;
    __syncthreads();
    mx = red[0];
    #pragma unroll
    for (int i = 1; i < 8; ++i) mx = fmaxf(mx, red[i]);
    __syncthreads();

    v.x = __expf(v.x - mx);
    v.y = __expf(v.y - mx);
    v.z = __expf(v.z - mx);
    v.w = __expf(v.w - mx);
    float sm = v.x + v.y + v.z + v.w;
    #pragma unroll
    for (int o = 16; o > 0; o >>= 1)
        sm += __shfl_xor_sync(0xFFFFFFFFu, sm, o);
    if ((t & 31) == 0) red[t >> 5] = sm;
    __syncthreads();
    sm = red[0];
    #pragma unroll
    for (int i = 1; i < 8; ++i) sm += red[i];

    const float inv = 1.f / sm;
    uint2 o;
    o.x = packbf(v.x * inv, v.y * inv);
    o.y = packbf(v.z * inv, v.w * inv);
    ((uint2*)(P + (long)blockIdx.x * HWD))[t] = o;
}

// ---------------------------------------------------------------------------
extern "C" void kernel_launch(void* const* d_in, const int* in_sizes, int n_in,
                              void* d_out, int out_size)
{
    const float* x  = (const float*)d_in[0];
    const float* Wq = (const float*)d_in[1];
    const float* bq = (const float*)d_in[2];
    const float* Wk = (const float*)d_in[3];
    const float* bk = (const float*)d_in[4];
    const float* Wv = (const float*)d_in[5];
    const float* bv = (const float*)d_in[6];
    const float* Wo = (const float*)d_in[7];
    const float* bo = (const float*)d_in[8];
    float* out = (float*)d_out;

    float *s, *bqkv;
    __nv_bfloat16 *xb, *qkv, *ab, *ob, *wbase;
    cudaGetSymbolAddress((void**)&s,    g_s);
    cudaGetSymbolAddress((void**)&xb,   g_xb);
    cudaGetSymbolAddress((void**)&qkv,  g_qkv);
    cudaGetSymbolAddress((void**)&ab,   g_ab);
    cudaGetSymbolAddress((void**)&ob,   g_ob);
    cudaGetSymbolAddress((void**)&wbase, g_w);
    cudaGetSymbolAddress((void**)&bqkv, g_bqkv);
    __nv_bfloat16* wqkv = wbase;                     // Wq|Wk|Wv = [1536][512]
    __nv_bfloat16* wo   = wbase + 3 * CDIM * CDIM;

    const long CHW  = (long)CDIM * HWD;
    const long QKVB = 3 * CHW;                       // per-batch qkv stride
    const long SHW  = (long)HWD * HWD;
    const int  SMEM = 3 * 32768;
    const dim3 blk(128);

    auto kProj  = gemm_bf16<true,  true,  CDIM, HWD, true,  false, false>;
    auto kScore = gemm_bf16<false, true,  HWD,  HWD, false, false, true >;
    auto kAV    = gemm_bf16<true,  false, HWD,  HWD, false, false, false>;
    auto kOut   = gemm_bf16<true,  true,  CDIM, HWD, true,  true,  true >;
    cudaFuncSetAttribute(kProj,  cudaFuncAttributeMaxDynamicSharedMemorySize, SMEM);
    cudaFuncSetAttribute(kScore, cudaFuncAttributeMaxDynamicSharedMemorySize, SMEM);
    cudaFuncSetAttribute(kAV,    cudaFuncAttributeMaxDynamicSharedMemorySize, SMEM);
    cudaFuncSetAttribute(kOut,   cudaFuncAttributeMaxDynamicSharedMemorySize, SMEM);

    // 0) converts + bias pack
    cvt_w_kernel<<<dim3(256, 4), 256>>>((const float4*)Wq, (const float4*)Wk,
                                        (const float4*)Wv, (const float4*)Wo,
                                        (uint2*)wbase);
    pack_bias_kernel<<<3, 512>>>(bq, bk, bv, bqkv);
    cvt_kernel<<<1024, 256>>>((const float4*)x, (uint2*)xb, (int)(CHW * BSZ / 4));

    // 1) fused QKV projection: qkv[b][m][i] = sum_c Wqkv[m][c]*x[b][c][i] + bias[m]
    {
        dim3 grd(HWD / 128, 3 * CDIM / 128, BSZ);
        kProj<<<grd, blk, SMEM>>>(wqkv, xb, qkv, CDIM, 0, CHW, QKVB,
                                  1.f, bqkv, nullptr, 0);
    }
    // 2) scores: s[b][i][j] = alpha * sum_c q[b][c][i]*k[b][c][j]
    {
        dim3 grd(HWD / 128, HWD / 128, BSZ);
        const float alpha = 1.0f / sqrtf((float)CDIM);
        kScore<<<grd, blk, SMEM>>>(qkv, qkv + CHW, s, CDIM, QKVB, QKVB, SHW,
                                   alpha, nullptr, nullptr, 0);
    }
    // 3) softmax -> bf16 attn
    softmax_kernel<<<BSZ * HWD, 256>>>(s, ab);

    // 4) attn @ V: ob[b][c][i] = sum_j v[b][c][j]*attn[b][i][j]
    {
        dim3 grd(HWD / 128, CDIM / 128, BSZ);
        kAV<<<grd, blk, SMEM>>>(qkv + 2 * CHW, ab, ob, HWD, QKVB, SHW, CHW,
                                1.f, nullptr, nullptr, 0);
    }
    // 5) output projection + bias + residual (fp32 out)
    {
        dim3 grd(HWD / 128, CDIM / 128, BSZ);
        kOut<<<grd, blk, SMEM>>>(wo, ob, out, CDIM, 0, CHW, CHW, 1.f,
                                 bo, x, CHW);
    }
}